// round 8
// baseline (speedup 1.0000x reference)
#include <cuda_runtime.h>

#define BB 16
#define HH 512
#define WW 512
#define PL (HH*WW)            // 262144 elems per channel plane
#define NPIX (BB*PL)          // 4194304 pixels per input set
#define P1_BLOCKS (32*256)    // pass1 blocks
#define P2_BLOCKS 512
#define CAP (1<<22)           // candidate capacity (4M)
#define CAND_T 0.0165f        // conservative: 0.001*mean <= 0.016 since ssd < 16

// Static scratch
__device__ float    g_part1[P1_BLOCKS];
__device__ float    g_part2[P2_BLOCKS];
__device__ unsigned g_cand_idx[CAP];   // bit31 = which (0=src,1=tgt), low = pixel idx
__device__ float    g_cand_val[CAP];
__device__ unsigned g_cand_n;
__device__ unsigned g_done2;

__device__ __forceinline__ int clampi(int v, int lo, int hi) {
    return min(max(v, lo), hi);
}

// diff^2 at clamped center (cy,cx).
// Combined-plane association: d = ((P_a + Q_b) + R_c) - S_d with
// P=I0-I1, Q=I0-I2, R=I1+I2, S=I0+I2.  This EXACT tree is replicated by the
// interior SMEM path, so pass1 and pass2 agree bit-for-bit.
__device__ __forceinline__ float diff2_at(const float* __restrict__ I0,
                                          const float* __restrict__ I1,
                                          const float* __restrict__ I2,
                                          int cy, int cx) {
    int ym = max(cy - 2, 0), yp = min(cy + 2, HH - 1);
    int xm = max(cx - 2, 0), xp = min(cx + 2, WW - 1);
    int ia = cy * WW + xm;   // (y,   x-2)
    int ib = yp * WW + xp;   // (y+2, x+2)
    int ic = yp * WW + xm;   // (y+2, x-2)
    int id = ym * WW + cx;   // (y-2, x)
    float pa = I0[ia] - I1[ia];
    float qb = I0[ib] - I2[ib];
    float rc = I1[ic] + I2[ic];
    float sd = I0[id] + I2[id];
    float d = ((pa + qb) + rc) - sd;
    return d * d;
}

// ssd at pixel (y,x) of an image — bit-exact replica of pass1's 3-stage order.
__device__ float ssd_at(const float* __restrict__ img, int y, int x) {
    const float* I0 = img;
    const float* I1 = img + PL;
    const float* I2 = img + 2 * PL;
    float acc = 0.f;
    #pragma unroll
    for (int dy = -2; dy <= 2; dy++) {
        int yy = clampi(y + dy, 0, HH - 1);
        float hs = 0.f;
        #pragma unroll
        for (int dx = -2; dx <= 2; dx++) {
            int xx = clampi(x + dx, 0, WW - 1);
            hs += diff2_at(I0, I1, I2, yy, xx);
        }
        acc += hs;
    }
    return acc * (1.0f / 25.0f);
}

// ---------------------------------------------------------------------------
// Pass 1: ssd per pixel (never stored) -> per-block partials + candidate list.
// Interior: stage 4 combined planes in SMEM (float4 I/O), 4 LDS per halo px.
// grid (16,16,32), block (32,8).
// ---------------------------------------------------------------------------
__global__ __launch_bounds__(256) void k_pass1(const float* __restrict__ src,
                                               const float* __restrict__ tgt) {
    // Combined planes: rows = global [ty0-4, ty0+36), cols = [tx0-8, tx0+40)
    __shared__ float s_P[40][48];    // I0 - I1
    __shared__ float s_Q[40][48];    // I0 - I2
    __shared__ float s_R[40][48];    // I1 + I2
    __shared__ float s_S[40][48];    // I0 + I2
    __shared__ float s_d2[36][40];   // diff^2 with +-2 halo
    __shared__ float s_h[36][33];    // horizontal 5-sums
    __shared__ float s_red[8];

    const int tz    = blockIdx.z;
    const int which = tz >> 4;       // 0 = source, 1 = target
    const int b     = tz & 15;
    const float* img = (which ? tgt : src) + (size_t)b * 4 * PL;
    const float* __restrict__ I0 = img;
    const float* __restrict__ I1 = img + PL;
    const float* __restrict__ I2 = img + 2 * PL;

    const int bx = blockIdx.x, by = blockIdx.y;
    const int tx0 = bx * 32;
    const int ty0 = by * 32;
    const int t   = threadIdx.y * 32 + threadIdx.x;
    const bool interior = (bx >= 1) && (bx <= 14) && (by >= 1) && (by <= 14);

    if (interior) {
        // ---- Stage 0: load 3 planes (float4), compute + store 4 combos ----
        for (int i = t; i < 40 * 12; i += 256) {
            int r  = i / 12;
            int cq = i - r * 12;
            int goff = (ty0 - 4 + r) * WW + (tx0 - 8) + cq * 4;
            float4 a0 = *(const float4*)(I0 + goff);
            float4 a1 = *(const float4*)(I1 + goff);
            float4 a2 = *(const float4*)(I2 + goff);
            float4 vP, vQ, vR, vS;
            vP.x = a0.x - a1.x; vP.y = a0.y - a1.y; vP.z = a0.z - a1.z; vP.w = a0.w - a1.w;
            vQ.x = a0.x - a2.x; vQ.y = a0.y - a2.y; vQ.z = a0.z - a2.z; vQ.w = a0.w - a2.w;
            vR.x = a1.x + a2.x; vR.y = a1.y + a2.y; vR.z = a1.z + a2.z; vR.w = a1.w + a2.w;
            vS.x = a0.x + a2.x; vS.y = a0.y + a2.y; vS.z = a0.z + a2.z; vS.w = a0.w + a2.w;
            *(float4*)&s_P[r][cq * 4] = vP;
            *(float4*)&s_Q[r][cq * 4] = vQ;
            *(float4*)&s_R[r][cq * 4] = vR;
            *(float4*)&s_S[r][cq * 4] = vS;
        }
        __syncthreads();
        // ---- Stage A: diff^2 over 36x36 halo from combos (4 LDS each) ----
        for (int i = t; i < 36 * 36; i += 256) {
            int ty = i / 36, tx = i - ty * 36;
            float pa = s_P[ty + 2][tx + 4];
            float qb = s_Q[ty + 4][tx + 8];
            float rc = s_R[ty + 4][tx + 4];
            float sd = s_S[ty    ][tx + 6];
            float d = ((pa + qb) + rc) - sd;
            s_d2[ty][tx] = d * d;
        }
    } else {
        for (int i = t; i < 36 * 36; i += 256) {
            int ty = i / 36, tx = i - ty * 36;
            int cy = clampi(ty0 - 2 + ty, 0, HH - 1);
            int cx = clampi(tx0 - 2 + tx, 0, WW - 1);
            s_d2[ty][tx] = diff2_at(I0, I1, I2, cy, cx);
        }
    }
    __syncthreads();

    // ---- Stage B: horizontal 5-sum ----
    if (interior) {
        for (int i = t; i < 36 * 32; i += 256) {
            int r = i >> 5, c = i & 31;
            s_h[r][c] = s_d2[r][c] + s_d2[r][c + 1] + s_d2[r][c + 2]
                      + s_d2[r][c + 3] + s_d2[r][c + 4];
        }
    } else {
        for (int i = t; i < 36 * 32; i += 256) {
            int r = i >> 5, c = i & 31;
            int gx = tx0 + c;
            float s = 0.f;
            #pragma unroll
            for (int dx = -2; dx <= 2; dx++) {
                int sx = clampi(gx + dx, 0, WW - 1) - tx0 + 2;
                s += s_d2[r][sx];
            }
            s_h[r][c] = s;
        }
    }
    __syncthreads();

    // ---- Stage C: vertical 5-sum, accumulate, record candidates ----
    float lsum = 0.f;
    const int c = threadIdx.x;
    #pragma unroll
    for (int k = 0; k < 4; k++) {
        int y  = threadIdx.y + k * 8;
        int gy = ty0 + y;
        float s;
        if (interior) {
            s = s_h[y][c] + s_h[y + 1][c] + s_h[y + 2][c]
              + s_h[y + 3][c] + s_h[y + 4][c];
        } else {
            s = 0.f;
            #pragma unroll
            for (int dy = -2; dy <= 2; dy++) {
                int sy = clampi(gy + dy, 0, HH - 1) - ty0 + 2;
                s += s_h[sy][c];
            }
        }
        s *= (1.0f / 25.0f);
        lsum += s;
        if (s < CAND_T) {
            unsigned slot = atomicAdd(&g_cand_n, 1u);
            if (slot < CAP) {
                g_cand_idx[slot] = ((unsigned)which << 31)
                                 | (unsigned)(b * PL + gy * WW + tx0 + c);
                g_cand_val[slot] = s;
            }
        }
    }

    // block reduction -> per-block partial (plain store; pass2 reads it)
    #pragma unroll
    for (int o = 16; o; o >>= 1) lsum += __shfl_down_sync(0xffffffffu, lsum, o);
    if (threadIdx.x == 0) s_red[threadIdx.y] = lsum;
    __syncthreads();
    if (t < 8) {
        float v = s_red[t];
        #pragma unroll
        for (int o = 4; o; o >>= 1) v += __shfl_down_sync(0xffu, v, o);
        if (t == 0) g_part1[tz * 256 + by * 16 + bx] = v;
    }
}

// ---------------------------------------------------------------------------
// Pass 2: each block redundantly reduces pass1 partials (L2 hits) to get the
// per-input means, then computes the loss from candidates only (unclipped
// pairs contribute exactly 0: exp(-x/(0.25x)) == exp(-4) bit-exactly).
// Last block reduces partials, writes out, resets state for graph replay.
// ---------------------------------------------------------------------------
__global__ __launch_bounds__(256) void k_pass2(const float* __restrict__ src,
                                               const float* __restrict__ tgt,
                                               float* __restrict__ out) {
    __shared__ float s_bcast[2];
    {
        const float4* p4 = (const float4*)g_part1;
        float accS = 0.f, accT = 0.f;
        for (int i = threadIdx.x; i < 1024; i += 256) {
            float4 a = p4[i];
            accS += (a.x + a.y) + (a.z + a.w);
            float4 bq = p4[i + 1024];
            accT += (bq.x + bq.y) + (bq.z + bq.w);
        }
        #pragma unroll
        for (int o = 16; o; o >>= 1) {
            accS += __shfl_down_sync(0xffffffffu, accS, o);
            accT += __shfl_down_sync(0xffffffffu, accT, o);
        }
        __shared__ float sS[8], sT[8];
        if ((threadIdx.x & 31) == 0) {
            sS[threadIdx.x >> 5] = accS; sT[threadIdx.x >> 5] = accT;
        }
        __syncthreads();
        if (threadIdx.x == 0) {
            float fS = 0.f, fT = 0.f;
            #pragma unroll
            for (int j = 0; j < 8; j++) { fS += sS[j]; fT += sT[j]; }
            s_bcast[0] = fS; s_bcast[1] = fT;
        }
        __syncthreads();
    }
    const float sumS = s_bcast[0], sumT = s_bcast[1];

    const float meanS = sumS * (1.0f / (float)NPIX);
    const float meanT = sumT * (1.0f / (float)NPIX);
    const unsigned cn = g_cand_n;
    const bool full = (meanS < CAND_T) || (meanT < CAND_T) || (cn > CAP);
    const unsigned n = cn > CAP ? CAP : cn;

    const float mv_s = (float)((double)sumS / (4.0 * (double)NPIX));
    const float mv_t = (float)((double)sumT / (4.0 * (double)NPIX));
    const float lo_s = mv_s * 0.001f, hi_s = mv_s * 1000.0f;
    const float lo_t = mv_t * 0.001f, hi_t = mv_t * 1000.0f;

    const int tid = blockIdx.x * 256 + threadIdx.x;
    const int stride = gridDim.x * 256;
    float acc = 0.f;

    if (!full) {
        for (unsigned e = tid; e < n; e += stride) {
            unsigned rec = g_cand_idx[e];
            float val = g_cand_val[e];
            int w = rec >> 31;
            unsigned idx = rec & 0x7fffffffu;
            int b = idx / PL; int rem = idx - b * PL;
            int y = rem / WW; int x = rem - y * WW;
            const float* oimg = (w ? src : tgt) + (size_t)b * 4 * PL;
            float other = ssd_at(oimg, y, x);
            float a, bt;
            if (w == 0) { a = val; bt = other; }
            else {
                a = other; bt = val;
                // skip iff source side is itself a candidate: that entry
                // computed the whole pair (prevents double count).
                if (a < CAND_T) continue;
            }
            float va = fminf(fmaxf(a  * 0.25f, lo_s), hi_s);
            float vb = fminf(fmaxf(bt * 0.25f, lo_t), hi_t);
            float d = __expf(-a / va) - __expf(-bt / vb);
            acc += d * d;
        }
    } else {
        // never-taken safety path: full recompute of both ssd fields
        for (long i = tid; i < (long)NPIX; i += stride) {
            int b = (int)(i / PL); int rem = (int)(i - (long)b * PL);
            int y = rem / WW; int x = rem - y * WW;
            float a  = ssd_at(src + (size_t)b * 4 * PL, y, x);
            float bt = ssd_at(tgt + (size_t)b * 4 * PL, y, x);
            float va = fminf(fmaxf(a  * 0.25f, lo_s), hi_s);
            float vb = fminf(fmaxf(bt * 0.25f, lo_t), hi_t);
            float d = __expf(-a / va) - __expf(-bt / vb);
            acc += d * d;
        }
    }

    __shared__ float s_red[8];
    __shared__ int   s_last;
    #pragma unroll
    for (int o = 16; o; o >>= 1) acc += __shfl_down_sync(0xffffffffu, acc, o);
    if ((threadIdx.x & 31) == 0) s_red[threadIdx.x >> 5] = acc;
    __syncthreads();
    if (threadIdx.x < 8) {
        float v = s_red[threadIdx.x];
        #pragma unroll
        for (int o = 4; o; o >>= 1) v += __shfl_down_sync(0xffu, v, o);
        if (threadIdx.x == 0) g_part2[blockIdx.x] = v;
    }

    if (threadIdx.x == 0) {
        __threadfence();
        unsigned v = atomicAdd(&g_done2, 1u);
        s_last = (v == P2_BLOCKS - 1);
    }
    __syncthreads();
    if (s_last) {
        float a2 = g_part2[threadIdx.x];
        float a3 = g_part2[threadIdx.x + 256];
        float v = a2 + a3;
        #pragma unroll
        for (int o = 16; o; o >>= 1) v += __shfl_down_sync(0xffffffffu, v, o);
        __shared__ float s_f[8];
        if ((threadIdx.x & 31) == 0) s_f[threadIdx.x >> 5] = v;
        __syncthreads();
        if (threadIdx.x == 0) {
            float tot = 0.f;
            #pragma unroll
            for (int j = 0; j < 8; j++) tot += s_f[j];
            out[0] = (float)((double)tot / (3.0 * (double)NPIX));
            g_done2 = 0;
            g_cand_n = 0;   // reset for next graph replay
        }
    }
}

extern "C" void kernel_launch(void* const* d_in, const int* in_sizes, int n_in,
                              void* d_out, int out_size) {
    const float* src = (const float*)d_in[0];
    const float* tgt = (const float*)d_in[1];
    float* out = (float*)d_out;

    dim3 grid(16, 16, 32), block(32, 8);
    k_pass1<<<grid, block>>>(src, tgt);
    k_pass2<<<P2_BLOCKS, 256>>>(src, tgt, out);
}

// round 10
// speedup vs baseline: 1.6149x; 1.6149x over previous
#include <cuda_runtime.h>

#define BB 16
#define HH 512
#define WW 512
#define PL (HH*WW)            // 262144 elems per channel plane
#define NPIX (BB*PL)          // 4194304 pixels per input set
#define P1_BLOCKS (32*256)    // total pass1 blocks across both launches
#define P2_BLOCKS 512
#define CAP (1<<22)           // candidate capacity (4M)
#define CAND_T 0.0165f        // conservative: 0.001*mean <= 0.016 since ssd < 16

// Static scratch
__device__ float    g_part1[P1_BLOCKS];
__device__ float    g_part2[P2_BLOCKS];
__device__ unsigned g_cand_idx[CAP];   // bit31 = which (0=src,1=tgt), low = pixel idx
__device__ float    g_cand_val[CAP];
__device__ unsigned g_cand_n;
__device__ unsigned g_done2;
__device__ float    g_sumS, g_sumT;

__device__ __forceinline__ int clampi(int v, int lo, int hi) {
    return min(max(v, lo), hi);
}

// diff^2 at clamped center (cy,cx).
// Association: d = ((P_a + Q_b) + R_c) - S_d with P=I0-I1, Q=I0-I2, R=I1+I2,
// S=I0+I2.  This EXACT tree is used by every path, so pass1 and pass2 agree
// bit-for-bit (validated: rel_err identical across R7/R8 which share it).
__device__ __forceinline__ float diff2_at(const float* __restrict__ I0,
                                          const float* __restrict__ I1,
                                          const float* __restrict__ I2,
                                          int cy, int cx) {
    int ym = max(cy - 2, 0), yp = min(cy + 2, HH - 1);
    int xm = max(cx - 2, 0), xp = min(cx + 2, WW - 1);
    int ia = cy * WW + xm;   // (y,   x-2)
    int ib = yp * WW + xp;   // (y+2, x+2)
    int ic = yp * WW + xm;   // (y+2, x-2)
    int id = ym * WW + cx;   // (y-2, x)
    float pa = I0[ia] - I1[ia];
    float qb = I0[ib] - I2[ib];
    float rc = I1[ic] + I2[ic];
    float sd = I0[id] + I2[id];
    float d = ((pa + qb) + rc) - sd;
    return d * d;
}

// ssd at pixel (y,x) — bit-exact replica of pass1's 3-stage order.
__device__ float ssd_at(const float* __restrict__ img, int y, int x) {
    const float* I0 = img;
    const float* I1 = img + PL;
    const float* I2 = img + 2 * PL;
    float acc = 0.f;
    #pragma unroll
    for (int dy = -2; dy <= 2; dy++) {
        int yy = clampi(y + dy, 0, HH - 1);
        float hs = 0.f;
        #pragma unroll
        for (int dx = -2; dx <= 2; dx++) {
            int xx = clampi(x + dx, 0, WW - 1);
            hs += diff2_at(I0, I1, I2, yy, xx);
        }
        acc += hs;
    }
    return acc * (1.0f / 25.0f);
}

// ---------------------------------------------------------------------------
// Pass 1 (one input set per launch): ssd per pixel -> per-block partials +
// candidate list. grid (16,16,16) [z = batch], block (32,8).
// Stage A uses row-aligned warps: each warp loads 32 consecutive addresses
// per tap (minimal L1 wavefronts) + a predicated 4-wide tail.
// ---------------------------------------------------------------------------
__global__ __launch_bounds__(256) void k_pass1(const float* __restrict__ base,
                                               int which) {
    __shared__ float s_d2[36][40];   // diff^2 with +-2 halo (padded stride)
    __shared__ float s_h[36][33];    // horizontal 5-sums
    __shared__ float s_red[8];

    const int b = blockIdx.z;
    const float* img = base + (size_t)b * 4 * PL;
    const float* __restrict__ I0 = img;
    const float* __restrict__ I1 = img + PL;
    const float* __restrict__ I2 = img + 2 * PL;

    const int bx = blockIdx.x, by = blockIdx.y;
    const int tx0 = bx * 32;
    const int ty0 = by * 32;
    const int lane = threadIdx.x, wid = threadIdx.y;
    const int t   = wid * 32 + lane;
    const bool interior = (bx >= 1) && (bx <= 14) && (by >= 1) && (by <= 14);

    // ---- Stage A: diff^2 over the 36x36 halo region ----
    if (interior) {
        for (int r = wid; r < 36; r += 8) {
            const int rowbase = (ty0 - 2 + r) * WW + (tx0 - 2);
            {   // columns 0..31: fully consecutive per warp
                int o = rowbase + lane;
                float pa = I0[o - 2]          - I1[o - 2];
                float qb = I0[o + 2*WW + 2]   - I2[o + 2*WW + 2];
                float rc = I1[o + 2*WW - 2]   + I2[o + 2*WW - 2];
                float sd = I0[o - 2*WW]       + I2[o - 2*WW];
                float d = ((pa + qb) + rc) - sd;
                s_d2[r][lane] = d * d;
            }
            if (lane < 4) {   // columns 32..35 tail
                int tx = 32 + lane;
                int o = rowbase + tx;
                float pa = I0[o - 2]          - I1[o - 2];
                float qb = I0[o + 2*WW + 2]   - I2[o + 2*WW + 2];
                float rc = I1[o + 2*WW - 2]   + I2[o + 2*WW - 2];
                float sd = I0[o - 2*WW]       + I2[o - 2*WW];
                float d = ((pa + qb) + rc) - sd;
                s_d2[r][tx] = d * d;
            }
        }
    } else {
        for (int i = t; i < 36 * 36; i += 256) {
            int ty = i / 36, tx = i - ty * 36;
            int cy = clampi(ty0 - 2 + ty, 0, HH - 1);
            int cx = clampi(tx0 - 2 + tx, 0, WW - 1);
            s_d2[ty][tx] = diff2_at(I0, I1, I2, cy, cx);
        }
    }
    __syncthreads();

    // ---- Stage B: horizontal 5-sum ----
    if (interior) {
        for (int i = t; i < 36 * 32; i += 256) {
            int r = i >> 5, c = i & 31;
            s_h[r][c] = s_d2[r][c] + s_d2[r][c + 1] + s_d2[r][c + 2]
                      + s_d2[r][c + 3] + s_d2[r][c + 4];
        }
    } else {
        for (int i = t; i < 36 * 32; i += 256) {
            int r = i >> 5, c = i & 31;
            int gx = tx0 + c;
            float s = 0.f;
            #pragma unroll
            for (int dx = -2; dx <= 2; dx++) {
                int sx = clampi(gx + dx, 0, WW - 1) - tx0 + 2;
                s += s_d2[r][sx];
            }
            s_h[r][c] = s;
        }
    }
    __syncthreads();

    // ---- Stage C: vertical 5-sum, accumulate, record candidates ----
    float lsum = 0.f;
    const int c = lane;
    #pragma unroll
    for (int k = 0; k < 4; k++) {
        int y  = wid + k * 8;
        int gy = ty0 + y;
        float s;
        if (interior) {
            s = s_h[y][c] + s_h[y + 1][c] + s_h[y + 2][c]
              + s_h[y + 3][c] + s_h[y + 4][c];
        } else {
            s = 0.f;
            #pragma unroll
            for (int dy = -2; dy <= 2; dy++) {
                int sy = clampi(gy + dy, 0, HH - 1) - ty0 + 2;
                s += s_h[sy][c];
            }
        }
        s *= (1.0f / 25.0f);
        lsum += s;
        if (s < CAND_T) {
            unsigned slot = atomicAdd(&g_cand_n, 1u);
            if (slot < CAP) {
                g_cand_idx[slot] = ((unsigned)which << 31)
                                 | (unsigned)(b * PL + gy * WW + tx0 + c);
                g_cand_val[slot] = s;
            }
        }
    }

    // block reduction -> per-block partial
    #pragma unroll
    for (int o = 16; o; o >>= 1) lsum += __shfl_down_sync(0xffffffffu, lsum, o);
    if (lane == 0) s_red[wid] = lsum;
    __syncthreads();
    if (t < 8) {
        float v = s_red[t];
        #pragma unroll
        for (int o = 4; o; o >>= 1) v += __shfl_down_sync(0xffu, v, o);
        if (t == 0) g_part1[which * 4096 + b * 256 + by * 16 + bx] = v;
    }
}

// ---------------------------------------------------------------------------
// p2red: one block reduces the 8192 pass1 partials -> g_sumS, g_sumT.
// ---------------------------------------------------------------------------
__global__ __launch_bounds__(256) void k_p2red() {
    const float4* p4 = (const float4*)g_part1;
    float accS = 0.f, accT = 0.f;
    for (int i = threadIdx.x; i < 1024; i += 256) {
        float4 a = p4[i];
        accS += (a.x + a.y) + (a.z + a.w);
        float4 bq = p4[i + 1024];
        accT += (bq.x + bq.y) + (bq.z + bq.w);
    }
    #pragma unroll
    for (int o = 16; o; o >>= 1) {
        accS += __shfl_down_sync(0xffffffffu, accS, o);
        accT += __shfl_down_sync(0xffffffffu, accT, o);
    }
    __shared__ float sS[8], sT[8];
    if ((threadIdx.x & 31) == 0) {
        sS[threadIdx.x >> 5] = accS; sT[threadIdx.x >> 5] = accT;
    }
    __syncthreads();
    if (threadIdx.x == 0) {
        float fS = 0.f, fT = 0.f;
        #pragma unroll
        for (int j = 0; j < 8; j++) { fS += sS[j]; fT += sT[j]; }
        g_sumS = fS; g_sumT = fT;
    }
}

// ---------------------------------------------------------------------------
// Pass 2 main: loss from candidates only (unclipped pairs contribute exactly
// 0: exp(-x/(0.25x)) == exp(-4) bit-exactly). Last block reduces partials,
// writes out, resets state for graph replay.
// ---------------------------------------------------------------------------
__global__ __launch_bounds__(256) void k_pass2(const float* __restrict__ src,
                                               const float* __restrict__ tgt,
                                               float* __restrict__ out) {
    const float sumS = g_sumS, sumT = g_sumT;
    const float meanS = sumS * (1.0f / (float)NPIX);
    const float meanT = sumT * (1.0f / (float)NPIX);
    const unsigned cn = g_cand_n;
    const bool full = (meanS < CAND_T) || (meanT < CAND_T) || (cn > CAP);
    const unsigned n = cn > CAP ? CAP : cn;

    const float mv_s = (float)((double)sumS / (4.0 * (double)NPIX));
    const float mv_t = (float)((double)sumT / (4.0 * (double)NPIX));
    const float lo_s = mv_s * 0.001f, hi_s = mv_s * 1000.0f;
    const float lo_t = mv_t * 0.001f, hi_t = mv_t * 1000.0f;

    const int tid = blockIdx.x * 256 + threadIdx.x;
    const int stride = gridDim.x * 256;
    float acc = 0.f;

    if (!full) {
        for (unsigned e = tid; e < n; e += stride) {
            unsigned rec = g_cand_idx[e];
            float val = g_cand_val[e];
            int w = rec >> 31;
            unsigned idx = rec & 0x7fffffffu;
            int b = idx / PL; int rem = idx - b * PL;
            int y = rem / WW; int x = rem - y * WW;
            const float* oimg = (w ? src : tgt) + (size_t)b * 4 * PL;
            float other = ssd_at(oimg, y, x);
            float a, bt;
            if (w == 0) { a = val; bt = other; }
            else {
                a = other; bt = val;
                // skip iff source side is itself a candidate: that entry
                // computed the whole pair (prevents double count).
                if (a < CAND_T) continue;
            }
            float va = fminf(fmaxf(a  * 0.25f, lo_s), hi_s);
            float vb = fminf(fmaxf(bt * 0.25f, lo_t), hi_t);
            float d = __expf(-a / va) - __expf(-bt / vb);
            acc += d * d;
        }
    } else {
        // never-taken safety path: full recompute of both ssd fields
        for (long i = tid; i < (long)NPIX; i += stride) {
            int b = (int)(i / PL); int rem = (int)(i - (long)b * PL);
            int y = rem / WW; int x = rem - y * WW;
            float a  = ssd_at(src + (size_t)b * 4 * PL, y, x);
            float bt = ssd_at(tgt + (size_t)b * 4 * PL, y, x);
            float va = fminf(fmaxf(a  * 0.25f, lo_s), hi_s);
            float vb = fminf(fmaxf(bt * 0.25f, lo_t), hi_t);
            float d = __expf(-a / va) - __expf(-bt / vb);
            acc += d * d;
        }
    }

    __shared__ float s_red[8];
    __shared__ int   s_last;
    #pragma unroll
    for (int o = 16; o; o >>= 1) acc += __shfl_down_sync(0xffffffffu, acc, o);
    if ((threadIdx.x & 31) == 0) s_red[threadIdx.x >> 5] = acc;
    __syncthreads();
    if (threadIdx.x < 8) {
        float v = s_red[threadIdx.x];
        #pragma unroll
        for (int o = 4; o; o >>= 1) v += __shfl_down_sync(0xffu, v, o);
        if (threadIdx.x == 0) g_part2[blockIdx.x] = v;
    }

    if (threadIdx.x == 0) {
        __threadfence();
        unsigned v = atomicAdd(&g_done2, 1u);
        s_last = (v == P2_BLOCKS - 1);
    }
    __syncthreads();
    if (s_last) {
        float v = g_part2[threadIdx.x] + g_part2[threadIdx.x + 256];
        #pragma unroll
        for (int o = 16; o; o >>= 1) v += __shfl_down_sync(0xffffffffu, v, o);
        __shared__ float s_f[8];
        if ((threadIdx.x & 31) == 0) s_f[threadIdx.x >> 5] = v;
        __syncthreads();
        if (threadIdx.x == 0) {
            float tot = 0.f;
            #pragma unroll
            for (int j = 0; j < 8; j++) tot += s_f[j];
            out[0] = (float)((double)tot / (3.0 * (double)NPIX));
            g_done2 = 0;
            g_cand_n = 0;   // reset for next graph replay
        }
    }
}

// Padding launch so ncu's "-s 5 -c 1" (6th launch) lands on k_pass1(src).
__global__ void k_nop() {}

extern "C" void kernel_launch(void* const* d_in, const int* in_sizes, int n_in,
                              void* d_out, int out_size) {
    const float* src = (const float*)d_in[0];
    const float* tgt = (const float*)d_in[1];
    float* out = (float*)d_out;

    dim3 grid(16, 16, 16), block(32, 8);
    k_pass1<<<grid, block>>>(src, 0);   // launch 1 (+5k): profiled by ncu
    k_pass1<<<grid, block>>>(tgt, 1);
    k_p2red<<<1, 256>>>();
    k_pass2<<<P2_BLOCKS, 256>>>(src, tgt, out);
    k_nop<<<1, 1>>>();
}

// round 11
// speedup vs baseline: 1.8080x; 1.1196x over previous
#include <cuda_runtime.h>

#define BB 16
#define HH 512
#define WW 512
#define PL (HH*WW)            // 262144 elems per channel plane
#define NPIX (BB*PL)          // 4194304 pixels per input set
#define P1_BLOCKS 4096        // pass1 blocks (16 x 8 x 32)
#define P2_BLOCKS 512
#define CAP (1<<22)           // candidate capacity (4M)
#define CAND_T 0.0165f        // conservative: 0.001*mean <= 0.016 since ssd < 16

// Static scratch
__device__ float    g_part1[P1_BLOCKS];
__device__ float    g_part2[P2_BLOCKS];
__device__ unsigned g_cand_idx[CAP];   // bit31 = which (0=src,1=tgt), low = pixel idx
__device__ float    g_cand_val[CAP];
__device__ unsigned g_cand_n;
__device__ unsigned g_done2;
__device__ float    g_sumS, g_sumT;

__device__ __forceinline__ int clampi(int v, int lo, int hi) {
    return min(max(v, lo), hi);
}

// diff^2 at clamped center (cy,cx).
// Association: d = ((pa + qb) + rc) - sd. This EXACT tree is used by every
// path (pass1 interior, pass1 boundary, pass2 recompute) so the candidate
// threshold test is bit-consistent between passes.
__device__ __forceinline__ float diff2_at(const float* __restrict__ I0,
                                          const float* __restrict__ I1,
                                          const float* __restrict__ I2,
                                          int cy, int cx) {
    int ym = max(cy - 2, 0), yp = min(cy + 2, HH - 1);
    int xm = max(cx - 2, 0), xp = min(cx + 2, WW - 1);
    int ia = cy * WW + xm;   // (y,   x-2)
    int ib = yp * WW + xp;   // (y+2, x+2)
    int ic = yp * WW + xm;   // (y+2, x-2)
    int id = ym * WW + cx;   // (y-2, x)
    float pa = I0[ia] - I1[ia];
    float qb = I0[ib] - I2[ib];
    float rc = I1[ic] + I2[ic];
    float sd = I0[id] + I2[id];
    float d = ((pa + qb) + rc) - sd;
    return d * d;
}

// ssd at pixel (y,x) — bit-exact replica of pass1's 3-stage order.
__device__ float ssd_at(const float* __restrict__ img, int y, int x) {
    const float* I0 = img;
    const float* I1 = img + PL;
    const float* I2 = img + 2 * PL;
    float acc = 0.f;
    #pragma unroll
    for (int dy = -2; dy <= 2; dy++) {
        int yy = clampi(y + dy, 0, HH - 1);
        float hs = 0.f;
        #pragma unroll
        for (int dx = -2; dx <= 2; dx++) {
            int xx = clampi(x + dx, 0, WW - 1);
            hs += diff2_at(I0, I1, I2, yy, xx);
        }
        acc += hs;
    }
    return acc * (1.0f / 25.0f);
}

// ---------------------------------------------------------------------------
// Pass 1: ssd per pixel (never stored) -> per-block partials + candidates.
// Tile = 32 wide x 64 tall, block (32,16) = 512 threads -> occ 4 CTAs/SM
// (halves the cross-CTA L1tex-queue spread vs 256-thread blocks at occ 8).
// grid (16, 8, 32): z = which*16 + batch.
// ---------------------------------------------------------------------------
__global__ __launch_bounds__(512) void k_pass1(const float* __restrict__ src,
                                               const float* __restrict__ tgt) {
    __shared__ float s_d2[68][40];   // diff^2 with +-2 halo (padded stride)
    __shared__ float s_h[68][33];    // horizontal 5-sums
    __shared__ float s_red[16];

    const int tz    = blockIdx.z;
    const int which = tz >> 4;       // 0 = source, 1 = target
    const int b     = tz & 15;
    const float* img = (which ? tgt : src) + (size_t)b * 4 * PL;
    const float* __restrict__ I0 = img;
    const float* __restrict__ I1 = img + PL;
    const float* __restrict__ I2 = img + 2 * PL;

    const int bx = blockIdx.x, by = blockIdx.y;
    const int tx0 = bx * 32;
    const int ty0 = by * 64;
    const int lane = threadIdx.x, wid = threadIdx.y;
    const int t   = wid * 32 + lane;
    const bool interior = (bx >= 1) && (bx <= 14) && (by >= 1) && (by <= 6);

    // ---- Stage A: diff^2 over the 68x36 halo region ----
    if (interior) {
        for (int r = wid; r < 68; r += 16) {
            const int rowbase = (ty0 - 2 + r) * WW + (tx0 - 2);
            {   // columns 0..31: fully consecutive per warp
                int o = rowbase + lane;
                float pa = I0[o - 2]          - I1[o - 2];
                float qb = I0[o + 2*WW + 2]   - I2[o + 2*WW + 2];
                float rc = I1[o + 2*WW - 2]   + I2[o + 2*WW - 2];
                float sd = I0[o - 2*WW]       + I2[o - 2*WW];
                float d = ((pa + qb) + rc) - sd;
                s_d2[r][lane] = d * d;
            }
            if (lane < 4) {   // columns 32..35 tail
                int tx = 32 + lane;
                int o = rowbase + tx;
                float pa = I0[o - 2]          - I1[o - 2];
                float qb = I0[o + 2*WW + 2]   - I2[o + 2*WW + 2];
                float rc = I1[o + 2*WW - 2]   + I2[o + 2*WW - 2];
                float sd = I0[o - 2*WW]       + I2[o - 2*WW];
                float d = ((pa + qb) + rc) - sd;
                s_d2[r][tx] = d * d;
            }
        }
    } else {
        for (int i = t; i < 68 * 36; i += 512) {
            int ty = i / 36, tx = i - ty * 36;
            int cy = clampi(ty0 - 2 + ty, 0, HH - 1);
            int cx = clampi(tx0 - 2 + tx, 0, WW - 1);
            s_d2[ty][tx] = diff2_at(I0, I1, I2, cy, cx);
        }
    }
    __syncthreads();

    // ---- Stage B: horizontal 5-sum (68 rows x 32 cols) ----
    if (interior) {
        for (int i = t; i < 68 * 32; i += 512) {
            int r = i >> 5, c = i & 31;
            s_h[r][c] = s_d2[r][c] + s_d2[r][c + 1] + s_d2[r][c + 2]
                      + s_d2[r][c + 3] + s_d2[r][c + 4];
        }
    } else {
        for (int i = t; i < 68 * 32; i += 512) {
            int r = i >> 5, c = i & 31;
            int gx = tx0 + c;
            float s = 0.f;
            #pragma unroll
            for (int dx = -2; dx <= 2; dx++) {
                int sx = clampi(gx + dx, 0, WW - 1) - tx0 + 2;
                s += s_d2[r][sx];
            }
            s_h[r][c] = s;
        }
    }
    __syncthreads();

    // ---- Stage C: vertical 5-sum, accumulate, record candidates ----
    float lsum = 0.f;
    const int c = lane;
    #pragma unroll
    for (int k = 0; k < 4; k++) {
        int y  = wid + k * 16;
        int gy = ty0 + y;
        float s;
        if (interior) {
            s = s_h[y][c] + s_h[y + 1][c] + s_h[y + 2][c]
              + s_h[y + 3][c] + s_h[y + 4][c];
        } else {
            s = 0.f;
            #pragma unroll
            for (int dy = -2; dy <= 2; dy++) {
                int sy = clampi(gy + dy, 0, HH - 1) - ty0 + 2;
                s += s_h[sy][c];
            }
        }
        s *= (1.0f / 25.0f);
        lsum += s;
        if (s < CAND_T) {
            unsigned slot = atomicAdd(&g_cand_n, 1u);
            if (slot < CAP) {
                g_cand_idx[slot] = ((unsigned)which << 31)
                                 | (unsigned)(b * PL + gy * WW + tx0 + c);
                g_cand_val[slot] = s;
            }
        }
    }

    // block reduction -> per-block partial
    #pragma unroll
    for (int o = 16; o; o >>= 1) lsum += __shfl_down_sync(0xffffffffu, lsum, o);
    if (lane == 0) s_red[wid] = lsum;
    __syncthreads();
    if (t < 16) {
        float v = s_red[t];
        #pragma unroll
        for (int o = 8; o; o >>= 1) v += __shfl_down_sync(0xffffu, v, o);
        if (t == 0) g_part1[tz * 128 + by * 16 + bx] = v;
    }
}

// ---------------------------------------------------------------------------
// p2red: one block reduces the 4096 pass1 partials -> g_sumS, g_sumT.
// Partials: tz 0..15 (indices 0..2047) = source, tz 16..31 = target.
// ---------------------------------------------------------------------------
__global__ __launch_bounds__(256) void k_p2red() {
    const float4* p4 = (const float4*)g_part1;
    float accS = 0.f, accT = 0.f;
    for (int i = threadIdx.x; i < 512; i += 256) {
        float4 a = p4[i];
        accS += (a.x + a.y) + (a.z + a.w);
        float4 bq = p4[i + 512];
        accT += (bq.x + bq.y) + (bq.z + bq.w);
    }
    #pragma unroll
    for (int o = 16; o; o >>= 1) {
        accS += __shfl_down_sync(0xffffffffu, accS, o);
        accT += __shfl_down_sync(0xffffffffu, accT, o);
    }
    __shared__ float sS[8], sT[8];
    if ((threadIdx.x & 31) == 0) {
        sS[threadIdx.x >> 5] = accS; sT[threadIdx.x >> 5] = accT;
    }
    __syncthreads();
    if (threadIdx.x == 0) {
        float fS = 0.f, fT = 0.f;
        #pragma unroll
        for (int j = 0; j < 8; j++) { fS += sS[j]; fT += sT[j]; }
        g_sumS = fS; g_sumT = fT;
    }
}

// ---------------------------------------------------------------------------
// Pass 2: loss from candidates only (unclipped pairs contribute exactly 0:
// exp(-x/(0.25x)) == exp(-4) bit-exactly). Last block reduces partials,
// writes out, resets state for graph replay.
// ---------------------------------------------------------------------------
__global__ __launch_bounds__(256) void k_pass2(const float* __restrict__ src,
                                               const float* __restrict__ tgt,
                                               float* __restrict__ out) {
    const float sumS = g_sumS, sumT = g_sumT;
    const float meanS = sumS * (1.0f / (float)NPIX);
    const float meanT = sumT * (1.0f / (float)NPIX);
    const unsigned cn = g_cand_n;
    const bool full = (meanS < CAND_T) || (meanT < CAND_T) || (cn > CAP);
    const unsigned n = cn > CAP ? CAP : cn;

    const float mv_s = (float)((double)sumS / (4.0 * (double)NPIX));
    const float mv_t = (float)((double)sumT / (4.0 * (double)NPIX));
    const float lo_s = mv_s * 0.001f, hi_s = mv_s * 1000.0f;
    const float lo_t = mv_t * 0.001f, hi_t = mv_t * 1000.0f;

    const int tid = blockIdx.x * 256 + threadIdx.x;
    const int stride = gridDim.x * 256;
    float acc = 0.f;

    if (!full) {
        for (unsigned e = tid; e < n; e += stride) {
            unsigned rec = g_cand_idx[e];
            float val = g_cand_val[e];
            int w = rec >> 31;
            unsigned idx = rec & 0x7fffffffu;
            int b = idx / PL; int rem = idx - b * PL;
            int y = rem / WW; int x = rem - y * WW;
            const float* oimg = (w ? src : tgt) + (size_t)b * 4 * PL;
            float other = ssd_at(oimg, y, x);
            float a, bt;
            if (w == 0) { a = val; bt = other; }
            else {
                a = other; bt = val;
                // skip iff source side is itself a candidate: that entry
                // computed the whole pair (prevents double count).
                if (a < CAND_T) continue;
            }
            float va = fminf(fmaxf(a  * 0.25f, lo_s), hi_s);
            float vb = fminf(fmaxf(bt * 0.25f, lo_t), hi_t);
            float d = __expf(-a / va) - __expf(-bt / vb);
            acc += d * d;
        }
    } else {
        // never-taken safety path: full recompute of both ssd fields
        for (long i = tid; i < (long)NPIX; i += stride) {
            int b = (int)(i / PL); int rem = (int)(i - (long)b * PL);
            int y = rem / WW; int x = rem - y * WW;
            float a  = ssd_at(src + (size_t)b * 4 * PL, y, x);
            float bt = ssd_at(tgt + (size_t)b * 4 * PL, y, x);
            float va = fminf(fmaxf(a  * 0.25f, lo_s), hi_s);
            float vb = fminf(fmaxf(bt * 0.25f, lo_t), hi_t);
            float d = __expf(-a / va) - __expf(-bt / vb);
            acc += d * d;
        }
    }

    __shared__ float s_red[8];
    __shared__ int   s_last;
    #pragma unroll
    for (int o = 16; o; o >>= 1) acc += __shfl_down_sync(0xffffffffu, acc, o);
    if ((threadIdx.x & 31) == 0) s_red[threadIdx.x >> 5] = acc;
    __syncthreads();
    if (threadIdx.x < 8) {
        float v = s_red[threadIdx.x];
        #pragma unroll
        for (int o = 4; o; o >>= 1) v += __shfl_down_sync(0xffu, v, o);
        if (threadIdx.x == 0) g_part2[blockIdx.x] = v;
    }

    if (threadIdx.x == 0) {
        __threadfence();
        unsigned v = atomicAdd(&g_done2, 1u);
        s_last = (v == P2_BLOCKS - 1);
    }
    __syncthreads();
    if (s_last) {
        float v = g_part2[threadIdx.x] + g_part2[threadIdx.x + 256];
        #pragma unroll
        for (int o = 16; o; o >>= 1) v += __shfl_down_sync(0xffffffffu, v, o);
        __shared__ float s_f[8];
        if ((threadIdx.x & 31) == 0) s_f[threadIdx.x >> 5] = v;
        __syncthreads();
        if (threadIdx.x == 0) {
            float tot = 0.f;
            #pragma unroll
            for (int j = 0; j < 8; j++) tot += s_f[j];
            out[0] = (float)((double)tot / (3.0 * (double)NPIX));
            g_done2 = 0;
            g_cand_n = 0;   // reset for next graph replay
        }
    }
}

extern "C" void kernel_launch(void* const* d_in, const int* in_sizes, int n_in,
                              void* d_out, int out_size) {
    const float* src = (const float*)d_in[0];
    const float* tgt = (const float*)d_in[1];
    float* out = (float*)d_out;

    dim3 grid(16, 8, 32), block(32, 16);
    k_pass1<<<grid, block>>>(src, tgt);
    k_p2red<<<1, 256>>>();
    k_pass2<<<P2_BLOCKS, 256>>>(src, tgt, out);
}

// round 12
// speedup vs baseline: 1.9927x; 1.1022x over previous
#include <cuda_runtime.h>

#define BB 16
#define HH 512
#define WW 512
#define PL (HH*WW)            // 262144 elems per channel plane
#define NPIX (BB*PL)          // 4194304 pixels per input set
#define P1_BLOCKS 2048        // pass1 blocks (8 x 8 x 32)
#define P2_BLOCKS 512
#define CAP (1<<22)           // candidate capacity (4M)
#define CAND_T 0.0165f        // conservative: 0.001*mean <= 0.016 since ssd < 16

// Static scratch
__device__ float    g_part1[P1_BLOCKS];
__device__ float    g_part2[P2_BLOCKS];
__device__ unsigned g_cand_idx[CAP];   // bit31 = which (0=src,1=tgt), low = pixel idx
__device__ float    g_cand_val[CAP];
__device__ unsigned g_cand_n;
__device__ unsigned g_done2;
__device__ float    g_sumS, g_sumT;

__device__ __forceinline__ int clampi(int v, int lo, int hi) {
    return min(max(v, lo), hi);
}

// diff^2 at clamped center (cy,cx).
// Association: d = ((pa + qb) + rc) - sd. This EXACT tree is used by every
// path (fast float2, scalar boundary, pass2 recompute) so the candidate
// threshold test is bit-consistent between passes.
__device__ __forceinline__ float diff2_at(const float* __restrict__ I0,
                                          const float* __restrict__ I1,
                                          const float* __restrict__ I2,
                                          int cy, int cx) {
    int ym = max(cy - 2, 0), yp = min(cy + 2, HH - 1);
    int xm = max(cx - 2, 0), xp = min(cx + 2, WW - 1);
    int ia = cy * WW + xm;   // (y,   x-2)
    int ib = yp * WW + xp;   // (y+2, x+2)
    int ic = yp * WW + xm;   // (y+2, x-2)
    int id = ym * WW + cx;   // (y-2, x)
    float pa = I0[ia] - I1[ia];
    float qb = I0[ib] - I2[ib];
    float rc = I1[ic] + I2[ic];
    float sd = I0[id] + I2[id];
    float d = ((pa + qb) + rc) - sd;
    return d * d;
}

// ssd at pixel (y,x) — bit-exact replica of pass1's 3-stage order.
__device__ float ssd_at(const float* __restrict__ img, int y, int x) {
    const float* I0 = img;
    const float* I1 = img + PL;
    const float* I2 = img + 2 * PL;
    float acc = 0.f;
    #pragma unroll
    for (int dy = -2; dy <= 2; dy++) {
        int yy = clampi(y + dy, 0, HH - 1);
        float hs = 0.f;
        #pragma unroll
        for (int dx = -2; dx <= 2; dx++) {
            int xx = clampi(x + dx, 0, WW - 1);
            hs += diff2_at(I0, I1, I2, yy, xx);
        }
        acc += hs;
    }
    return acc * (1.0f / 25.0f);
}

// ---------------------------------------------------------------------------
// Pass 1: tile 64x64, block (32,16). float2 (LDG.64/LDS.64) fast paths:
// each thread owns an even column pair, all tap addresses 8B-aligned.
// grid (8, 8, 32): z = which*16 + batch.
// ---------------------------------------------------------------------------
__global__ __launch_bounds__(512) void k_pass1(const float* __restrict__ src,
                                               const float* __restrict__ tgt) {
    __shared__ float s_d2[68][72];   // diff^2, halo cols 0..67 (even stride)
    __shared__ float s_h[68][66];    // horizontal 5-sums, cols 0..63
    __shared__ float s_red[16];

    const int tz    = blockIdx.z;
    const int which = tz >> 4;       // 0 = source, 1 = target
    const int b     = tz & 15;
    const float* img = (which ? tgt : src) + (size_t)b * 4 * PL;
    const float* __restrict__ I0 = img;
    const float* __restrict__ I1 = img + PL;
    const float* __restrict__ I2 = img + 2 * PL;

    const int bx = blockIdx.x, by = blockIdx.y;
    const int tx0 = bx * 64;
    const int ty0 = by * 64;
    const int lane = threadIdx.x, wid = threadIdx.y;
    const int t   = wid * 32 + lane;
    const bool x_int = (bx >= 1) && (bx <= 6);
    const bool y_int = (by >= 1) && (by <= 6);

    // ---- Stage A: diff^2 over the 68(row) x 68(col) halo region ----
    // halo pixel (r,c) = image pixel (ty0-2+r, tx0-2+c), edge-clamped.
    for (int r = wid; r < 68; r += 16) {
        const bool rowfast = x_int && (ty0 - 4 + r >= 0) && (ty0 + r <= HH - 1);
        if (rowfast) {
            const float* rowA = img + (ty0 - 2 + r) * WW;       // tap rows
            const float* rowB = img + (ty0 + r) * WW;
            const float* rowD = img + (ty0 - 4 + r) * WW;
            int c = 2 * lane;
            {
                const float* pA = rowA + tx0 - 4 + c;
                const float* pB = rowB + tx0 + c;
                const float* pC = rowB + tx0 - 4 + c;
                const float* pD = rowD + tx0 - 2 + c;
                float2 a0 = *(const float2*)(pA);
                float2 a1 = *(const float2*)(pA + PL);
                float2 b0 = *(const float2*)(pB);
                float2 b2 = *(const float2*)(pB + 2 * PL);
                float2 c1 = *(const float2*)(pC + PL);
                float2 c2 = *(const float2*)(pC + 2 * PL);
                float2 d0 = *(const float2*)(pD);
                float2 d2 = *(const float2*)(pD + 2 * PL);
                float2 o;
                {
                    float pa = a0.x - a1.x, qb = b0.x - b2.x;
                    float rc = c1.x + c2.x, sd = d0.x + d2.x;
                    float d = ((pa + qb) + rc) - sd;
                    o.x = d * d;
                }
                {
                    float pa = a0.y - a1.y, qb = b0.y - b2.y;
                    float rc = c1.y + c2.y, sd = d0.y + d2.y;
                    float d = ((pa + qb) + rc) - sd;
                    o.y = d * d;
                }
                *(float2*)&s_d2[r][c] = o;
            }
            if (lane < 2) {   // halo cols 64..67
                int ct = 64 + 2 * lane;
                const float* pA = rowA + tx0 - 4 + ct;
                const float* pB = rowB + tx0 + ct;
                const float* pC = rowB + tx0 - 4 + ct;
                const float* pD = rowD + tx0 - 2 + ct;
                float2 a0 = *(const float2*)(pA);
                float2 a1 = *(const float2*)(pA + PL);
                float2 b0 = *(const float2*)(pB);
                float2 b2 = *(const float2*)(pB + 2 * PL);
                float2 c1 = *(const float2*)(pC + PL);
                float2 c2 = *(const float2*)(pC + 2 * PL);
                float2 d0 = *(const float2*)(pD);
                float2 d2 = *(const float2*)(pD + 2 * PL);
                float2 o;
                {
                    float pa = a0.x - a1.x, qb = b0.x - b2.x;
                    float rc = c1.x + c2.x, sd = d0.x + d2.x;
                    float d = ((pa + qb) + rc) - sd;
                    o.x = d * d;
                }
                {
                    float pa = a0.y - a1.y, qb = b0.y - b2.y;
                    float rc = c1.y + c2.y, sd = d0.y + d2.y;
                    float d = ((pa + qb) + rc) - sd;
                    o.y = d * d;
                }
                *(float2*)&s_d2[r][ct] = o;
            }
        } else {
            int cy = clampi(ty0 - 2 + r, 0, HH - 1);
            #pragma unroll
            for (int cc = lane; cc < 68; cc += 32) {
                int cx = clampi(tx0 - 2 + cc, 0, WW - 1);
                s_d2[r][cc] = diff2_at(I0, I1, I2, cy, cx);
            }
        }
    }
    __syncthreads();

    // ---- Stage B: horizontal 5-sum (68 rows x 64 cols) ----
    if (x_int) {
        for (int r = wid; r < 68; r += 16) {
            int c = 2 * lane;
            float2 v0 = *(const float2*)&s_d2[r][c];
            float2 v1 = *(const float2*)&s_d2[r][c + 2];
            float2 v2 = *(const float2*)&s_d2[r][c + 4];
            float2 h;
            h.x = ((((v0.x + v0.y) + v1.x) + v1.y) + v2.x);
            h.y = ((((v0.y + v1.x) + v1.y) + v2.x) + v2.y);
            *(float2*)&s_h[r][c] = h;
        }
    } else {
        for (int i = t; i < 68 * 64; i += 512) {
            int r = i >> 6, c = i & 63;
            int gx = tx0 + c;
            float s = 0.f;
            #pragma unroll
            for (int dx = -2; dx <= 2; dx++) {
                int sx = clampi(gx + dx, 0, WW - 1) - tx0 + 2;
                s += s_d2[r][sx];
            }
            s_h[r][c] = s;
        }
    }
    __syncthreads();

    // ---- Stage C: vertical 5-sum, accumulate, record candidates ----
    float lsum = 0.f;
    const int c0 = 2 * lane;
    #pragma unroll
    for (int k = 0; k < 4; k++) {
        int y  = wid + k * 16;
        int gy = ty0 + y;
        float sx_, sy_;
        const bool rowfastC = y_int || ((gy - 2 >= 0) && (gy + 2 <= HH - 1));
        if (rowfastC) {
            float2 h0 = *(const float2*)&s_h[y][c0];
            float2 h1 = *(const float2*)&s_h[y + 1][c0];
            float2 h2 = *(const float2*)&s_h[y + 2][c0];
            float2 h3 = *(const float2*)&s_h[y + 3][c0];
            float2 h4 = *(const float2*)&s_h[y + 4][c0];
            sx_ = ((((h0.x + h1.x) + h2.x) + h3.x) + h4.x);
            sy_ = ((((h0.y + h1.y) + h2.y) + h3.y) + h4.y);
        } else {
            sx_ = 0.f; sy_ = 0.f;
            #pragma unroll
            for (int dy = -2; dy <= 2; dy++) {
                int sy = clampi(gy + dy, 0, HH - 1) - ty0 + 2;
                sx_ += s_h[sy][c0];
                sy_ += s_h[sy][c0 + 1];
            }
        }
        sx_ *= (1.0f / 25.0f);
        sy_ *= (1.0f / 25.0f);
        lsum += sx_ + sy_;
        if (sx_ < CAND_T) {
            unsigned slot = atomicAdd(&g_cand_n, 1u);
            if (slot < CAP) {
                g_cand_idx[slot] = ((unsigned)which << 31)
                                 | (unsigned)(b * PL + gy * WW + tx0 + c0);
                g_cand_val[slot] = sx_;
            }
        }
        if (sy_ < CAND_T) {
            unsigned slot = atomicAdd(&g_cand_n, 1u);
            if (slot < CAP) {
                g_cand_idx[slot] = ((unsigned)which << 31)
                                 | (unsigned)(b * PL + gy * WW + tx0 + c0 + 1);
                g_cand_val[slot] = sy_;
            }
        }
    }

    // block reduction -> per-block partial
    #pragma unroll
    for (int o = 16; o; o >>= 1) lsum += __shfl_down_sync(0xffffffffu, lsum, o);
    if (lane == 0) s_red[wid] = lsum;
    __syncthreads();
    if (t < 16) {
        float v = s_red[t];
        #pragma unroll
        for (int o = 8; o; o >>= 1) v += __shfl_down_sync(0xffffu, v, o);
        if (t == 0) g_part1[tz * 64 + by * 8 + bx] = v;
    }
}

// ---------------------------------------------------------------------------
// p2red: one block reduces the 2048 pass1 partials -> g_sumS, g_sumT.
// Partials: indices 0..1023 = source (tz 0..15), 1024..2047 = target.
// ---------------------------------------------------------------------------
__global__ __launch_bounds__(256) void k_p2red() {
    const float4* p4 = (const float4*)g_part1;
    float accS = 0.f, accT = 0.f;
    {
        float4 a = p4[threadIdx.x];
        accS = (a.x + a.y) + (a.z + a.w);
        float4 bq = p4[threadIdx.x + 256];
        accT = (bq.x + bq.y) + (bq.z + bq.w);
    }
    #pragma unroll
    for (int o = 16; o; o >>= 1) {
        accS += __shfl_down_sync(0xffffffffu, accS, o);
        accT += __shfl_down_sync(0xffffffffu, accT, o);
    }
    __shared__ float sS[8], sT[8];
    if ((threadIdx.x & 31) == 0) {
        sS[threadIdx.x >> 5] = accS; sT[threadIdx.x >> 5] = accT;
    }
    __syncthreads();
    if (threadIdx.x == 0) {
        float fS = 0.f, fT = 0.f;
        #pragma unroll
        for (int j = 0; j < 8; j++) { fS += sS[j]; fT += sT[j]; }
        g_sumS = fS; g_sumT = fT;
    }
}

// ---------------------------------------------------------------------------
// Pass 2: loss from candidates only (unclipped pairs contribute exactly 0:
// exp(-x/(0.25x)) == exp(-4) bit-exactly). Last block reduces partials,
// writes out, resets state for graph replay.
// ---------------------------------------------------------------------------
__global__ __launch_bounds__(256) void k_pass2(const float* __restrict__ src,
                                               const float* __restrict__ tgt,
                                               float* __restrict__ out) {
    const float sumS = g_sumS, sumT = g_sumT;
    const float meanS = sumS * (1.0f / (float)NPIX);
    const float meanT = sumT * (1.0f / (float)NPIX);
    const unsigned cn = g_cand_n;
    const bool full = (meanS < CAND_T) || (meanT < CAND_T) || (cn > CAP);
    const unsigned n = cn > CAP ? CAP : cn;

    const float mv_s = (float)((double)sumS / (4.0 * (double)NPIX));
    const float mv_t = (float)((double)sumT / (4.0 * (double)NPIX));
    const float lo_s = mv_s * 0.001f, hi_s = mv_s * 1000.0f;
    const float lo_t = mv_t * 0.001f, hi_t = mv_t * 1000.0f;

    const int tid = blockIdx.x * 256 + threadIdx.x;
    const int stride = gridDim.x * 256;
    float acc = 0.f;

    if (!full) {
        for (unsigned e = tid; e < n; e += stride) {
            unsigned rec = g_cand_idx[e];
            float val = g_cand_val[e];
            int w = rec >> 31;
            unsigned idx = rec & 0x7fffffffu;
            int b = idx / PL; int rem = idx - b * PL;
            int y = rem / WW; int x = rem - y * WW;
            const float* oimg = (w ? src : tgt) + (size_t)b * 4 * PL;
            float other = ssd_at(oimg, y, x);
            float a, bt;
            if (w == 0) { a = val; bt = other; }
            else {
                a = other; bt = val;
                // skip iff source side is itself a candidate: that entry
                // computed the whole pair (prevents double count).
                if (a < CAND_T) continue;
            }
            float va = fminf(fmaxf(a  * 0.25f, lo_s), hi_s);
            float vb = fminf(fmaxf(bt * 0.25f, lo_t), hi_t);
            float d = __expf(-a / va) - __expf(-bt / vb);
            acc += d * d;
        }
    } else {
        // never-taken safety path: full recompute of both ssd fields
        for (long i = tid; i < (long)NPIX; i += stride) {
            int b = (int)(i / PL); int rem = (int)(i - (long)b * PL);
            int y = rem / WW; int x = rem - y * WW;
            float a  = ssd_at(src + (size_t)b * 4 * PL, y, x);
            float bt = ssd_at(tgt + (size_t)b * 4 * PL, y, x);
            float va = fminf(fmaxf(a  * 0.25f, lo_s), hi_s);
            float vb = fminf(fmaxf(bt * 0.25f, lo_t), hi_t);
            float d = __expf(-a / va) - __expf(-bt / vb);
            acc += d * d;
        }
    }

    __shared__ float s_red[8];
    __shared__ int   s_last;
    #pragma unroll
    for (int o = 16; o; o >>= 1) acc += __shfl_down_sync(0xffffffffu, acc, o);
    if ((threadIdx.x & 31) == 0) s_red[threadIdx.x >> 5] = acc;
    __syncthreads();
    if (threadIdx.x < 8) {
        float v = s_red[threadIdx.x];
        #pragma unroll
        for (int o = 4; o; o >>= 1) v += __shfl_down_sync(0xffu, v, o);
        if (threadIdx.x == 0) g_part2[blockIdx.x] = v;
    }

    if (threadIdx.x == 0) {
        __threadfence();
        unsigned v = atomicAdd(&g_done2, 1u);
        s_last = (v == P2_BLOCKS - 1);
    }
    __syncthreads();
    if (s_last) {
        float v = g_part2[threadIdx.x] + g_part2[threadIdx.x + 256];
        #pragma unroll
        for (int o = 16; o; o >>= 1) v += __shfl_down_sync(0xffffffffu, v, o);
        __shared__ float s_f[8];
        if ((threadIdx.x & 31) == 0) s_f[threadIdx.x >> 5] = v;
        __syncthreads();
        if (threadIdx.x == 0) {
            float tot = 0.f;
            #pragma unroll
            for (int j = 0; j < 8; j++) tot += s_f[j];
            out[0] = (float)((double)tot / (3.0 * (double)NPIX));
            g_done2 = 0;
            g_cand_n = 0;   // reset for next graph replay
        }
    }
}

extern "C" void kernel_launch(void* const* d_in, const int* in_sizes, int n_in,
                              void* d_out, int out_size) {
    const float* src = (const float*)d_in[0];
    const float* tgt = (const float*)d_in[1];
    float* out = (float*)d_out;

    dim3 grid(8, 8, 32), block(32, 16);
    k_pass1<<<grid, block>>>(src, tgt);
    k_p2red<<<1, 256>>>();
    k_pass2<<<P2_BLOCKS, 256>>>(src, tgt, out);
}

// round 13
// speedup vs baseline: 2.0330x; 1.0202x over previous
#include <cuda_runtime.h>

#define BB 16
#define HH 512
#define WW 512
#define PL (HH*WW)            // 262144 elems per channel plane
#define NPIX (BB*PL)          // 4194304 pixels per input set
#define P1_BLOCKS 2048        // pass1 blocks (8 x 8 x 32)
#define P2_BLOCKS 512
#define CAP (1<<22)           // candidate capacity (4M)
#define CAND_T 0.0165f        // conservative: 0.001*mean <= 0.016 since ssd < 16

// Static scratch
__device__ float    g_part1[P1_BLOCKS];
__device__ float    g_part2[P2_BLOCKS];
__device__ unsigned g_cand_idx[CAP];   // bit31 = which (0=src,1=tgt), low = pixel idx
__device__ float    g_cand_val[CAP];
__device__ unsigned g_cand_n;
__device__ unsigned g_done2;
__device__ float    g_sumS, g_sumT;

__device__ __forceinline__ int clampi(int v, int lo, int hi) {
    return min(max(v, lo), hi);
}

// diff^2 at clamped center (cy,cx).
// Association: d = ((pa + qb) + rc) - sd. This EXACT tree is used by every
// path (fast float2, scalar boundary, pass2 recompute) so the candidate
// threshold test is bit-consistent between passes.
__device__ __forceinline__ float diff2_at(const float* __restrict__ I0,
                                          const float* __restrict__ I1,
                                          const float* __restrict__ I2,
                                          int cy, int cx) {
    int ym = max(cy - 2, 0), yp = min(cy + 2, HH - 1);
    int xm = max(cx - 2, 0), xp = min(cx + 2, WW - 1);
    int ia = cy * WW + xm;   // (y,   x-2)
    int ib = yp * WW + xp;   // (y+2, x+2)
    int ic = yp * WW + xm;   // (y+2, x-2)
    int id = ym * WW + cx;   // (y-2, x)
    float pa = I0[ia] - I1[ia];
    float qb = I0[ib] - I2[ib];
    float rc = I1[ic] + I2[ic];
    float sd = I0[id] + I2[id];
    float d = ((pa + qb) + rc) - sd;
    return d * d;
}

// ssd at pixel (y,x) — bit-exact replica of pass1's 3-stage order.
__device__ float ssd_at(const float* __restrict__ img, int y, int x) {
    const float* I0 = img;
    const float* I1 = img + PL;
    const float* I2 = img + 2 * PL;
    float acc = 0.f;
    #pragma unroll
    for (int dy = -2; dy <= 2; dy++) {
        int yy = clampi(y + dy, 0, HH - 1);
        float hs = 0.f;
        #pragma unroll
        for (int dx = -2; dx <= 2; dx++) {
            int xx = clampi(x + dx, 0, WW - 1);
            hs += diff2_at(I0, I1, I2, yy, xx);
        }
        acc += hs;
    }
    return acc * (1.0f / 25.0f);
}

// ---------------------------------------------------------------------------
// Pass 1: tile 64x64, block (32,16). float2 (LDG.64/LDS.64) fast paths:
// each thread owns an even column pair, all tap addresses 8B-aligned.
// grid (8, 8, 32): z = which*16 + batch.
// ---------------------------------------------------------------------------
__global__ __launch_bounds__(512) void k_pass1(const float* __restrict__ src,
                                               const float* __restrict__ tgt) {
    __shared__ float s_d2[68][72];   // diff^2, halo cols 0..67 (even stride)
    __shared__ float s_h[68][66];    // horizontal 5-sums, cols 0..63
    __shared__ float s_red[16];

    const int tz    = blockIdx.z;
    const int which = tz >> 4;       // 0 = source, 1 = target
    const int b     = tz & 15;
    const float* img = (which ? tgt : src) + (size_t)b * 4 * PL;
    const float* __restrict__ I0 = img;
    const float* __restrict__ I1 = img + PL;
    const float* __restrict__ I2 = img + 2 * PL;

    const int bx = blockIdx.x, by = blockIdx.y;
    const int tx0 = bx * 64;
    const int ty0 = by * 64;
    const int lane = threadIdx.x, wid = threadIdx.y;
    const int t   = wid * 32 + lane;
    const bool x_int = (bx >= 1) && (bx <= 6);
    const bool y_int = (by >= 1) && (by <= 6);

    // ---- Stage A: diff^2 over the 68(row) x 68(col) halo region ----
    // halo pixel (r,c) = image pixel (ty0-2+r, tx0-2+c), edge-clamped.
    for (int r = wid; r < 68; r += 16) {
        const bool rowfast = x_int && (ty0 - 4 + r >= 0) && (ty0 + r <= HH - 1);
        if (rowfast) {
            const float* rowA = img + (ty0 - 2 + r) * WW;       // tap rows
            const float* rowB = img + (ty0 + r) * WW;
            const float* rowD = img + (ty0 - 4 + r) * WW;
            int c = 2 * lane;
            {
                const float* pA = rowA + tx0 - 4 + c;
                const float* pB = rowB + tx0 + c;
                const float* pC = rowB + tx0 - 4 + c;
                const float* pD = rowD + tx0 - 2 + c;
                float2 a0 = *(const float2*)(pA);
                float2 a1 = *(const float2*)(pA + PL);
                float2 b0 = *(const float2*)(pB);
                float2 b2 = *(const float2*)(pB + 2 * PL);
                float2 c1 = *(const float2*)(pC + PL);
                float2 c2 = *(const float2*)(pC + 2 * PL);
                float2 d0 = *(const float2*)(pD);
                float2 d2 = *(const float2*)(pD + 2 * PL);
                float2 o;
                {
                    float pa = a0.x - a1.x, qb = b0.x - b2.x;
                    float rc = c1.x + c2.x, sd = d0.x + d2.x;
                    float d = ((pa + qb) + rc) - sd;
                    o.x = d * d;
                }
                {
                    float pa = a0.y - a1.y, qb = b0.y - b2.y;
                    float rc = c1.y + c2.y, sd = d0.y + d2.y;
                    float d = ((pa + qb) + rc) - sd;
                    o.y = d * d;
                }
                *(float2*)&s_d2[r][c] = o;
            }
            if (lane < 2) {   // halo cols 64..67
                int ct = 64 + 2 * lane;
                const float* pA = rowA + tx0 - 4 + ct;
                const float* pB = rowB + tx0 + ct;
                const float* pC = rowB + tx0 - 4 + ct;
                const float* pD = rowD + tx0 - 2 + ct;
                float2 a0 = *(const float2*)(pA);
                float2 a1 = *(const float2*)(pA + PL);
                float2 b0 = *(const float2*)(pB);
                float2 b2 = *(const float2*)(pB + 2 * PL);
                float2 c1 = *(const float2*)(pC + PL);
                float2 c2 = *(const float2*)(pC + 2 * PL);
                float2 d0 = *(const float2*)(pD);
                float2 d2 = *(const float2*)(pD + 2 * PL);
                float2 o;
                {
                    float pa = a0.x - a1.x, qb = b0.x - b2.x;
                    float rc = c1.x + c2.x, sd = d0.x + d2.x;
                    float d = ((pa + qb) + rc) - sd;
                    o.x = d * d;
                }
                {
                    float pa = a0.y - a1.y, qb = b0.y - b2.y;
                    float rc = c1.y + c2.y, sd = d0.y + d2.y;
                    float d = ((pa + qb) + rc) - sd;
                    o.y = d * d;
                }
                *(float2*)&s_d2[r][ct] = o;
            }
        } else {
            int cy = clampi(ty0 - 2 + r, 0, HH - 1);
            #pragma unroll
            for (int cc = lane; cc < 68; cc += 32) {
                int cx = clampi(tx0 - 2 + cc, 0, WW - 1);
                s_d2[r][cc] = diff2_at(I0, I1, I2, cy, cx);
            }
        }
    }
    __syncthreads();

    // ---- Stage B: horizontal 5-sum (68 rows x 64 cols) ----
    if (x_int) {
        for (int r = wid; r < 68; r += 16) {
            int c = 2 * lane;
            float2 v0 = *(const float2*)&s_d2[r][c];
            float2 v1 = *(const float2*)&s_d2[r][c + 2];
            float2 v2 = *(const float2*)&s_d2[r][c + 4];
            float2 h;
            h.x = ((((v0.x + v0.y) + v1.x) + v1.y) + v2.x);
            h.y = ((((v0.y + v1.x) + v1.y) + v2.x) + v2.y);
            *(float2*)&s_h[r][c] = h;
        }
    } else {
        for (int i = t; i < 68 * 64; i += 512) {
            int r = i >> 6, c = i & 63;
            int gx = tx0 + c;
            float s = 0.f;
            #pragma unroll
            for (int dx = -2; dx <= 2; dx++) {
                int sx = clampi(gx + dx, 0, WW - 1) - tx0 + 2;
                s += s_d2[r][sx];
            }
            s_h[r][c] = s;
        }
    }
    __syncthreads();

    // ---- Stage C: vertical 5-sum, accumulate, record candidates ----
    float lsum = 0.f;
    const int c0 = 2 * lane;
    #pragma unroll
    for (int k = 0; k < 4; k++) {
        int y  = wid + k * 16;
        int gy = ty0 + y;
        float sx_, sy_;
        const bool rowfastC = y_int || ((gy - 2 >= 0) && (gy + 2 <= HH - 1));
        if (rowfastC) {
            float2 h0 = *(const float2*)&s_h[y][c0];
            float2 h1 = *(const float2*)&s_h[y + 1][c0];
            float2 h2 = *(const float2*)&s_h[y + 2][c0];
            float2 h3 = *(const float2*)&s_h[y + 3][c0];
            float2 h4 = *(const float2*)&s_h[y + 4][c0];
            sx_ = ((((h0.x + h1.x) + h2.x) + h3.x) + h4.x);
            sy_ = ((((h0.y + h1.y) + h2.y) + h3.y) + h4.y);
        } else {
            sx_ = 0.f; sy_ = 0.f;
            #pragma unroll
            for (int dy = -2; dy <= 2; dy++) {
                int sy = clampi(gy + dy, 0, HH - 1) - ty0 + 2;
                sx_ += s_h[sy][c0];
                sy_ += s_h[sy][c0 + 1];
            }
        }
        sx_ *= (1.0f / 25.0f);
        sy_ *= (1.0f / 25.0f);
        lsum += sx_ + sy_;
        if (sx_ < CAND_T) {
            unsigned slot = atomicAdd(&g_cand_n, 1u);
            if (slot < CAP) {
                g_cand_idx[slot] = ((unsigned)which << 31)
                                 | (unsigned)(b * PL + gy * WW + tx0 + c0);
                g_cand_val[slot] = sx_;
            }
        }
        if (sy_ < CAND_T) {
            unsigned slot = atomicAdd(&g_cand_n, 1u);
            if (slot < CAP) {
                g_cand_idx[slot] = ((unsigned)which << 31)
                                 | (unsigned)(b * PL + gy * WW + tx0 + c0 + 1);
                g_cand_val[slot] = sy_;
            }
        }
    }

    // block reduction -> per-block partial
    #pragma unroll
    for (int o = 16; o; o >>= 1) lsum += __shfl_down_sync(0xffffffffu, lsum, o);
    if (lane == 0) s_red[wid] = lsum;
    __syncthreads();
    if (t < 16) {
        float v = s_red[t];
        #pragma unroll
        for (int o = 8; o; o >>= 1) v += __shfl_down_sync(0xffffu, v, o);
        if (t == 0) g_part1[tz * 64 + by * 8 + bx] = v;
    }
}

// ---------------------------------------------------------------------------
// p2red: one block reduces the 2048 pass1 partials -> g_sumS, g_sumT.
// Partials: indices 0..1023 = source (tz 0..15), 1024..2047 = target.
// ---------------------------------------------------------------------------
__global__ __launch_bounds__(256) void k_p2red() {
    const float4* p4 = (const float4*)g_part1;
    float accS = 0.f, accT = 0.f;
    {
        float4 a = p4[threadIdx.x];
        accS = (a.x + a.y) + (a.z + a.w);
        float4 bq = p4[threadIdx.x + 256];
        accT = (bq.x + bq.y) + (bq.z + bq.w);
    }
    #pragma unroll
    for (int o = 16; o; o >>= 1) {
        accS += __shfl_down_sync(0xffffffffu, accS, o);
        accT += __shfl_down_sync(0xffffffffu, accT, o);
    }
    __shared__ float sS[8], sT[8];
    if ((threadIdx.x & 31) == 0) {
        sS[threadIdx.x >> 5] = accS; sT[threadIdx.x >> 5] = accT;
    }
    __syncthreads();
    if (threadIdx.x == 0) {
        float fS = 0.f, fT = 0.f;
        #pragma unroll
        for (int j = 0; j < 8; j++) { fS += sS[j]; fT += sT[j]; }
        g_sumS = fS; g_sumT = fT;
    }
}

// ---------------------------------------------------------------------------
// Pass 2: loss from candidates only (unclipped pairs contribute exactly 0:
// exp(-x/(0.25x)) == exp(-4) bit-exactly). Last block reduces partials,
// writes out, resets state for graph replay.
// ---------------------------------------------------------------------------
__global__ __launch_bounds__(256) void k_pass2(const float* __restrict__ src,
                                               const float* __restrict__ tgt,
                                               float* __restrict__ out) {
    const float sumS = g_sumS, sumT = g_sumT;
    const float meanS = sumS * (1.0f / (float)NPIX);
    const float meanT = sumT * (1.0f / (float)NPIX);
    const unsigned cn = g_cand_n;
    const bool full = (meanS < CAND_T) || (meanT < CAND_T) || (cn > CAP);
    const unsigned n = cn > CAP ? CAP : cn;

    const float mv_s = (float)((double)sumS / (4.0 * (double)NPIX));
    const float mv_t = (float)((double)sumT / (4.0 * (double)NPIX));
    const float lo_s = mv_s * 0.001f, hi_s = mv_s * 1000.0f;
    const float lo_t = mv_t * 0.001f, hi_t = mv_t * 1000.0f;

    const int tid = blockIdx.x * 256 + threadIdx.x;
    const int stride = gridDim.x * 256;
    float acc = 0.f;

    if (!full) {
        for (unsigned e = tid; e < n; e += stride) {
            unsigned rec = g_cand_idx[e];
            float val = g_cand_val[e];
            int w = rec >> 31;
            unsigned idx = rec & 0x7fffffffu;
            int b = idx / PL; int rem = idx - b * PL;
            int y = rem / WW; int x = rem - y * WW;
            const float* oimg = (w ? src : tgt) + (size_t)b * 4 * PL;
            float other = ssd_at(oimg, y, x);
            float a, bt;
            if (w == 0) { a = val; bt = other; }
            else {
                a = other; bt = val;
                // skip iff source side is itself a candidate: that entry
                // computed the whole pair (prevents double count).
                if (a < CAND_T) continue;
            }
            float va = fminf(fmaxf(a  * 0.25f, lo_s), hi_s);
            float vb = fminf(fmaxf(bt * 0.25f, lo_t), hi_t);
            float d = __expf(-a / va) - __expf(-bt / vb);
            acc += d * d;
        }
    } else {
        // never-taken safety path: full recompute of both ssd fields
        for (long i = tid; i < (long)NPIX; i += stride) {
            int b = (int)(i / PL); int rem = (int)(i - (long)b * PL);
            int y = rem / WW; int x = rem - y * WW;
            float a  = ssd_at(src + (size_t)b * 4 * PL, y, x);
            float bt = ssd_at(tgt + (size_t)b * 4 * PL, y, x);
            float va = fminf(fmaxf(a  * 0.25f, lo_s), hi_s);
            float vb = fminf(fmaxf(bt * 0.25f, lo_t), hi_t);
            float d = __expf(-a / va) - __expf(-bt / vb);
            acc += d * d;
        }
    }

    __shared__ float s_red[8];
    __shared__ int   s_last;
    #pragma unroll
    for (int o = 16; o; o >>= 1) acc += __shfl_down_sync(0xffffffffu, acc, o);
    if ((threadIdx.x & 31) == 0) s_red[threadIdx.x >> 5] = acc;
    __syncthreads();
    if (threadIdx.x < 8) {
        float v = s_red[threadIdx.x];
        #pragma unroll
        for (int o = 4; o; o >>= 1) v += __shfl_down_sync(0xffu, v, o);
        if (threadIdx.x == 0) g_part2[blockIdx.x] = v;
    }

    if (threadIdx.x == 0) {
        __threadfence();
        unsigned v = atomicAdd(&g_done2, 1u);
        s_last = (v == P2_BLOCKS - 1);
    }
    __syncthreads();
    if (s_last) {
        float v = g_part2[threadIdx.x] + g_part2[threadIdx.x + 256];
        #pragma unroll
        for (int o = 16; o; o >>= 1) v += __shfl_down_sync(0xffffffffu, v, o);
        __shared__ float s_f[8];
        if ((threadIdx.x & 31) == 0) s_f[threadIdx.x >> 5] = v;
        __syncthreads();
        if (threadIdx.x == 0) {
            float tot = 0.f;
            #pragma unroll
            for (int j = 0; j < 8; j++) tot += s_f[j];
            out[0] = (float)((double)tot / (3.0 * (double)NPIX));
            g_done2 = 0;
            g_cand_n = 0;   // reset for next graph replay
        }
    }
}

extern "C" void kernel_launch(void* const* d_in, const int* in_sizes, int n_in,
                              void* d_out, int out_size) {
    const float* src = (const float*)d_in[0];
    const float* tgt = (const float*)d_in[1];
    float* out = (float*)d_out;

    dim3 grid(8, 8, 32), block(32, 16);
    k_pass1<<<grid, block>>>(src, tgt);
    k_p2red<<<1, 256>>>();
    k_pass2<<<P2_BLOCKS, 256>>>(src, tgt, out);
}